// round 1
// baseline (speedup 1.0000x reference)
#include <cuda_runtime.h>
#include <cstdint>
#include <math.h>

// Problem constants
#define BB 16
#define SS 256
#define VV 32000
#define HH 1024
#define MM (SS*BB)        // 4096 rows in time-major order m = s*16+b
#define G4 (4*HH)         // 4096 packed gate columns

// ---------------- scratch (static device memory; no allocation) ----------------
__device__ float g_WhP[G4*HH];      // packed+row-major recurrent weights  [p][k]
__device__ float g_WxP[G4*HH];      // packed input weights                [p][k]
__device__ float g_bpack[G4];
__device__ int   g_arow[MM];        // token id per GEMM row m
__device__ float g_xpart[(size_t)MM*G4];  // 64MB: x@Wx.T + b, per (s,b)
__device__ float g_ys[(size_t)MM*HH];     // h history for projection
__device__ float g_h[BB*HH];              // current h
__device__ unsigned long long g_bar = 0ULL;

// ---------------- pack kernel ----------------
__global__ void pack_kernel(const float* __restrict__ Wi, const float* __restrict__ Wf,
                            const float* __restrict__ Wo, const float* __restrict__ Wc,
                            const float* __restrict__ bi, const float* __restrict__ bf,
                            const float* __restrict__ bo, const float* __restrict__ bc,
                            const int* __restrict__ x)
{
    size_t idx = (size_t)blockIdx.x*256 + threadIdx.x;   // over G4*HH
    if (idx < (size_t)G4*HH) {
        int p = (int)(idx >> 10);
        int k = (int)(idx & 1023);
        int n = p >> 2, gt = p & 3;
        const float* W = (gt==0)?Wi:(gt==1)?Wf:(gt==2)?Wo:Wc;
        g_WhP[idx] = W[(size_t)n*2048 + k];
        g_WxP[idx] = W[(size_t)n*2048 + 1024 + k];
        if (k == 0) {
            const float* bbp = (gt==0)?bi:(gt==1)?bf:(gt==2)?bo:bc;
            g_bpack[p] = bbp[n];
        }
    }
    if (idx < MM) {
        // m = s*16 + b  ->  token = x[b*256 + s]
        int m = (int)idx;
        g_arow[m] = x[(m & 15)*SS + (m >> 4)];
    }
}

// ---------------- shared NT SGEMM: C[m][n] = sum_k A[m][k]*B[n][k] + bias[n] ----------------
// MODE 0: A = emb gathered via g_arow, B = g_WxP, bias = g_bpack, C = g_xpart (N=4096)
// MODE 1: A = g_ys,                    B = emb,   bias = fcb,     C = d_out remapped (N=32000)
#define BM 128
#define BN 128
#define BK 16

template<int MODE, int NN>
__global__ void __launch_bounds__(256) sgemm_nt(const float* __restrict__ emb,
                                                const float* __restrict__ bias,
                                                float* __restrict__ C)
{
    __shared__ float As[BK][BM];
    __shared__ float Bs[BK][BN];
    const int tid = threadIdx.x;
    const int bm = blockIdx.x, bn = blockIdx.y;
    const int tx = tid & 15, ty = tid >> 4;

    // each thread loads rows r0 and r0+64 of both tiles, float4 q
    const int r0 = tid >> 2;
    const int q  = tid & 3;

    const float* aptr0; const float* aptr1;
    {
        int gm0 = bm*BM + r0, gm1 = bm*BM + r0 + 64;
        if (MODE == 0) {
            aptr0 = emb + (size_t)g_arow[gm0]*HH;
            aptr1 = emb + (size_t)g_arow[gm1]*HH;
        } else {
            aptr0 = g_ys + (size_t)gm0*HH;
            aptr1 = g_ys + (size_t)gm1*HH;
        }
    }
    const float* Bbase = (MODE == 0) ? g_WxP : emb;
    const float* bptr0 = Bbase + (size_t)(bn*BN + r0)*HH;
    const float* bptr1 = Bbase + (size_t)(bn*BN + r0 + 64)*HH;

    float acc[8][8];
    #pragma unroll
    for (int i = 0; i < 8; i++)
        #pragma unroll
        for (int j = 0; j < 8; j++) acc[i][j] = 0.f;

    for (int kt = 0; kt < HH; kt += BK) {
        float4 av0 = *(const float4*)(aptr0 + kt + q*4);
        float4 av1 = *(const float4*)(aptr1 + kt + q*4);
        float4 bv0 = *(const float4*)(bptr0 + kt + q*4);
        float4 bv1 = *(const float4*)(bptr1 + kt + q*4);
        As[q*4+0][r0] = av0.x; As[q*4+1][r0] = av0.y; As[q*4+2][r0] = av0.z; As[q*4+3][r0] = av0.w;
        As[q*4+0][r0+64] = av1.x; As[q*4+1][r0+64] = av1.y; As[q*4+2][r0+64] = av1.z; As[q*4+3][r0+64] = av1.w;
        Bs[q*4+0][r0] = bv0.x; Bs[q*4+1][r0] = bv0.y; Bs[q*4+2][r0] = bv0.z; Bs[q*4+3][r0] = bv0.w;
        Bs[q*4+0][r0+64] = bv1.x; Bs[q*4+1][r0+64] = bv1.y; Bs[q*4+2][r0+64] = bv1.z; Bs[q*4+3][r0+64] = bv1.w;
        __syncthreads();
        #pragma unroll
        for (int kk = 0; kk < BK; kk++) {
            float a[8], w[8];
            *(float4*)&a[0] = *(const float4*)&As[kk][ty*8];
            *(float4*)&a[4] = *(const float4*)&As[kk][ty*8+4];
            *(float4*)&w[0] = *(const float4*)&Bs[kk][tx*8];
            *(float4*)&w[4] = *(const float4*)&Bs[kk][tx*8+4];
            #pragma unroll
            for (int i = 0; i < 8; i++)
                #pragma unroll
                for (int j = 0; j < 8; j++)
                    acc[i][j] += a[i]*w[j];
        }
        __syncthreads();
    }

    const float* bsrc = (MODE == 0) ? g_bpack : bias;
    float bfrag[8];
    #pragma unroll
    for (int j = 0; j < 8; j++) bfrag[j] = bsrc[bn*BN + tx*8 + j];

    #pragma unroll
    for (int i = 0; i < 8; i++) {
        int m = bm*BM + ty*8 + i;
        size_t rowoff;
        float* Cb;
        if (MODE == 0) { rowoff = (size_t)m * G4; Cb = g_xpart; }
        else { rowoff = (size_t)((m & 15)*SS + (m >> 4)) * (size_t)NN; Cb = C; }
        float* Cp = Cb + rowoff + bn*BN + tx*8;
        float4 o0, o1;
        o0.x = acc[i][0]+bfrag[0]; o0.y = acc[i][1]+bfrag[1];
        o0.z = acc[i][2]+bfrag[2]; o0.w = acc[i][3]+bfrag[3];
        o1.x = acc[i][4]+bfrag[4]; o1.y = acc[i][5]+bfrag[5];
        o1.z = acc[i][6]+bfrag[6]; o1.w = acc[i][7]+bfrag[7];
        *(float4*)(Cp)   = o0;
        *(float4*)(Cp+4) = o1;
    }
}

// ---------------- persistent recurrent kernel ----------------
#define GRID_R 128
#define THR_R  256
#define WSH_STRIDE 36
#define HS_STRIDE  20
#define RED_STRIDE 36
#define SMEM_BYTES ((HH*WSH_STRIDE + HH*HS_STRIDE)*4)

__device__ __forceinline__ void grid_barrier() {
    __syncthreads();
    if (threadIdx.x == 0) {
        __threadfence();
        unsigned long long ticket = atomicAdd(&g_bar, 1ULL);
        unsigned long long target = (ticket / GRID_R + 1ULL) * (unsigned long long)GRID_R;
        while (*((volatile unsigned long long*)&g_bar) < target) { }
        __threadfence();
    }
    __syncthreads();
}

__global__ void __launch_bounds__(THR_R, 1) lstm_rec(float* __restrict__ out_hc)
{
    extern __shared__ float sm[];
    float* Wsh = sm;                        // [k][c], stride 36, 147456 B
    float* hs  = sm + HH*WSH_STRIDE;        // [k][b], stride 20 (reused as red buffer)

    const int tid = threadIdx.x;
    const int cta = blockIdx.x;
    const int tk = tid & 31;
    const int tb = (tid >> 5) & 1;
    const int tc = tid >> 6;
    const int b0 = tb*8, c0 = tc*8;

    // fill Wsh: this CTA owns packed cols [cta*32, cta*32+32)
    {
        int c = tid >> 3, kq = tid & 7;
        const float* src = g_WhP + (size_t)(cta*32 + c)*HH;
        #pragma unroll 4
        for (int it = 0; it < 32; it++) {
            int k0 = kq*4 + it*32;
            float4 v = *(const float4*)(src + k0);
            Wsh[(k0+0)*WSH_STRIDE + c] = v.x;
            Wsh[(k0+1)*WSH_STRIDE + c] = v.y;
            Wsh[(k0+2)*WSH_STRIDE + c] = v.z;
            Wsh[(k0+3)*WSH_STRIDE + c] = v.w;
        }
    }
    // zero this CTA's slice of h
    if (tid < 128) g_h[cta*128 + tid] = 0.f;

    float c_state = 0.f;   // threads tid<128 own (b=tid&15, n_local=tid>>4)

    grid_barrier();

    for (int s = 0; s < SS; s++) {
        // load h (all 16x1024) into hs, L1-bypassing (cross-SM producer)
        {
            int b = tid >> 4, nq = tid & 15;
            const float* hp = g_h + b*HH;
            #pragma unroll 4
            for (int it = 0; it < 16; it++) {
                int n0 = nq*4 + it*64;
                float4 v = __ldcg((const float4*)(hp + n0));
                hs[(n0+0)*HS_STRIDE + b] = v.x;
                hs[(n0+1)*HS_STRIDE + b] = v.y;
                hs[(n0+2)*HS_STRIDE + b] = v.z;
                hs[(n0+3)*HS_STRIDE + b] = v.w;
            }
        }
        __syncthreads();

        // GEMM: acc[bi][cj] = sum over this thread's k-slice of h[b][k]*Wh[c][k]
        float acc[8][8];
        #pragma unroll
        for (int i = 0; i < 8; i++)
            #pragma unroll
            for (int j = 0; j < 8; j++) acc[i][j] = 0.f;

        #pragma unroll 4
        for (int kk = 0; kk < 32; kk++) {
            int k = kk*32 + tk;
            float a[8], w[8];
            *(float4*)&a[0] = *(const float4*)&hs[k*HS_STRIDE + b0];
            *(float4*)&a[4] = *(const float4*)&hs[k*HS_STRIDE + b0 + 4];
            *(float4*)&w[0] = *(const float4*)&Wsh[k*WSH_STRIDE + c0];
            *(float4*)&w[4] = *(const float4*)&Wsh[k*WSH_STRIDE + c0 + 4];
            #pragma unroll
            for (int i = 0; i < 8; i++)
                #pragma unroll
                for (int j = 0; j < 8; j++)
                    acc[i][j] += a[i]*w[j];
        }
        __syncthreads();   // done reading hs; reuse as reduction buffer

        float* red = hs;
        #pragma unroll
        for (int i = 0; i < 8; i++)
            #pragma unroll
            for (int j = 0; j < 8; j++)
                red[((c0+j)*16 + (b0+i))*RED_STRIDE + tk] = acc[i][j];
        __syncthreads();

        if (tid < 128) {
            int b = tid & 15, nl = tid >> 4;
            float g[4];
            #pragma unroll
            for (int gt = 0; gt < 4; gt++) {
                int cl = nl*4 + gt;
                const float* rp = red + (cl*16 + b)*RED_STRIDE;
                float ssum = 0.f;
                #pragma unroll
                for (int t = 0; t < 32; t += 4) {
                    float4 v = *(const float4*)(rp + t);
                    ssum += (v.x + v.y) + (v.z + v.w);
                }
                g[gt] = ssum + __ldcg(&g_xpart[((size_t)s*BB + b)*G4 + cta*32 + cl]);
            }
            float i_g = 1.f/(1.f + expf(-g[0]));
            float f_g = 1.f/(1.f + expf(-g[1]));
            float o_g = 1.f/(1.f + expf(-g[2]));
            float cc  = tanhf(g[3]);
            c_state = f_g*c_state + i_g*cc;
            float h_new = o_g * tanhf(c_state);
            int n = cta*8 + nl;
            g_h[b*HH + n] = h_new;
            g_ys[((size_t)s*BB + b)*HH + n] = h_new;
            if (s == SS-1) {
                const size_t OUT_H = (size_t)BB*SS*VV;
                out_hc[OUT_H + (size_t)b*HH + n] = h_new;
                out_hc[OUT_H + (size_t)BB*HH + (size_t)b*HH + n] = c_state;
            }
        }
        grid_barrier();
    }
}

// ---------------- launch ----------------
extern "C" void kernel_launch(void* const* d_in, const int* in_sizes, int n_in,
                              void* d_out, int out_size)
{
    const int*   x   = (const int*)  d_in[0];
    const float* emb = (const float*)d_in[1];
    const float* Wi  = (const float*)d_in[2];
    const float* bi  = (const float*)d_in[3];
    const float* Wf  = (const float*)d_in[4];
    const float* bf  = (const float*)d_in[5];
    const float* Wo  = (const float*)d_in[6];
    const float* bo  = (const float*)d_in[7];
    const float* Wc  = (const float*)d_in[8];
    const float* bc  = (const float*)d_in[9];
    const float* fcb = (const float*)d_in[10];
    float* out = (float*)d_out;

    cudaFuncSetAttribute(lstm_rec, cudaFuncAttributeMaxDynamicSharedMemorySize, SMEM_BYTES);

    // 1) pack weights into gate-interleaved layout + token row index
    pack_kernel<<<(G4*HH + 255)/256, 256>>>(Wi, Wf, Wo, Wc, bi, bf, bo, bc, x);

    // 2) x-part: xpart[m][p] = emb[tok[m]] . WxP[p] + bpack[p]
    sgemm_nt<0, G4><<<dim3(MM/BM, G4/BN), 256>>>(emb, nullptr, nullptr);

    // 3) recurrent scan (persistent, grid-synced)
    lstm_rec<<<GRID_R, THR_R, SMEM_BYTES>>>(out);

    // 4) tied output projection: logits[b][s][v] = ys[m] . emb[v] + fcb[v]
    sgemm_nt<1, VV><<<dim3(MM/BM, VV/BN), 256>>>(emb, fcb, out);
}